// round 1
// baseline (speedup 1.0000x reference)
#include <cuda_runtime.h>
#include <math.h>

// Problem constants
#define NE 8
#define NH 2048
#define NI 2816
#define NT 512
#define NPAIR 1024   // NT * top-k(2)

// ---------------- scratch (device globals; no allocation allowed) ----------
__device__ __align__(256) float g_act[(size_t)NPAIR * NI];   // grouped-by-expert activations
__device__ __align__(256) float g_outp[(size_t)NPAIR * NH];  // per-ORIGINAL-pair expert outputs
__device__ int g_cnt[NE];
__device__ int g_off[NE];
__device__ int g_cur[NE];
__device__ int g_tok[NPAIR];   // pos -> token
__device__ int g_orig[NPAIR];  // pos -> original pair id (t*2 + k)

// ---------------- routing ---------------------------------------------------
// Builds per-expert contiguous lists of (token, orig-pair) entries.
// Auto-detects int64 vs int32 topk_ids: if every odd 32-bit word of the first
// 1024 words is zero, the buffer is little-endian int64 (values < 8).
__global__ void route_kernel(const void* __restrict__ ids_raw) {
    __shared__ int s_or;
    int tid = threadIdx.x;
    if (tid == 0) s_or = 0;
    if (tid < NE) { g_cnt[tid] = 0; g_cur[tid] = 0; }
    __syncthreads();

    const int* i32 = (const int*)ids_raw;
    int acc = 0;
    for (int i = 1 + 2 * tid; i < NPAIR; i += 2 * blockDim.x) acc |= i32[i];
    atomicOr(&s_or, acc);
    __syncthreads();
    const bool is64 = (s_or == 0);
    const long long* i64 = (const long long*)ids_raw;

    for (int p = tid; p < NPAIR; p += blockDim.x) {
        int e = is64 ? (int)i64[p] : i32[p];
        atomicAdd(&g_cnt[e], 1);
    }
    __syncthreads();
    if (tid == 0) {
        int o = 0;
        for (int e = 0; e < NE; e++) { g_off[e] = o; o += g_cnt[e]; }
    }
    __syncthreads();
    for (int p = tid; p < NPAIR; p += blockDim.x) {
        int e = is64 ? (int)i64[p] : i32[p];
        int pos = g_off[e] + atomicAdd(&g_cur[e], 1);
        g_tok[pos]  = p >> 1;
        g_orig[pos] = p;
    }
}

// ---------------- GEMM tiling params ----------------------------------------
#define TM 64
#define TN 64
#define TKK 16
// 256 threads; thread (tx,ty) owns m = m0+ty+16i, n = n0+tx+16j (i,j in 0..3)

// ---------------- GEMM1: act = silu(x @ Wg^T) * (x @ Wu^T) ------------------
// w13 rows [0,I) are gate, rows [I,2I) are up. Block computes both tiles so
// the SwiGLU epilogue fuses in-register. Block scales applied on SMEM load
// (constant scalar per tile per k-chunk since tiles never cross 128 blocks).
__global__ __launch_bounds__(256) void gemm1_kernel(
    const float* __restrict__ x,
    const float* __restrict__ w13,
    const float* __restrict__ s13)
{
    int e   = blockIdx.y;
    int cnt = g_cnt[e];
    int m0  = blockIdx.z * TM;
    if (m0 >= cnt) return;
    int off = g_off[e];
    int n0  = blockIdx.x * TN;   // n in [0, NI)

    __shared__ float As[TKK][TM];
    __shared__ float Bg[TKK][TN];
    __shared__ float Bu[TKK][TN];

    int tid = threadIdx.x;
    int tx = tid & 15;
    int ty = tid >> 4;

    // loader mapping: each thread loads one float4 per tile per k-chunk
    int lr = tid >> 2;           // row within tile: 0..63
    int lk = (tid & 3) << 2;     // k offset: 0,4,8,12

    int am  = m0 + lr;
    int tok = g_tok[off + (am < cnt ? am : 0)];
    const float* xrow = x   + (size_t)tok * NH;
    const float* wg   = w13 + ((size_t)e * (2 * NI) + (size_t)(n0 + lr)) * NH;
    const float* wu   = w13 + ((size_t)e * (2 * NI) + (size_t)(NI + n0 + lr)) * NH;
    const float* se   = s13 + (size_t)e * (2 * NI / 128) * (NH / 128);
    int sgBase = (n0 >> 7) * (NH / 128);
    int suBase = ((n0 + NI) >> 7) * (NH / 128);

    float cg[4][4], cu[4][4];
    #pragma unroll
    for (int i = 0; i < 4; i++)
        #pragma unroll
        for (int j = 0; j < 4; j++) { cg[i][j] = 0.f; cu[i][j] = 0.f; }

    for (int k0 = 0; k0 < NH; k0 += TKK) {
        float4 av  = *(const float4*)(xrow + k0 + lk);
        float4 bgv = *(const float4*)(wg + k0 + lk);
        float4 buv = *(const float4*)(wu + k0 + lk);
        float sg = se[sgBase + (k0 >> 7)];
        float su = se[suBase + (k0 >> 7)];
        __syncthreads();
        As[lk + 0][lr] = av.x;  As[lk + 1][lr] = av.y;
        As[lk + 2][lr] = av.z;  As[lk + 3][lr] = av.w;
        Bg[lk + 0][lr] = bgv.x * sg; Bg[lk + 1][lr] = bgv.y * sg;
        Bg[lk + 2][lr] = bgv.z * sg; Bg[lk + 3][lr] = bgv.w * sg;
        Bu[lk + 0][lr] = buv.x * su; Bu[lk + 1][lr] = buv.y * su;
        Bu[lk + 2][lr] = buv.z * su; Bu[lk + 3][lr] = buv.w * su;
        __syncthreads();
        #pragma unroll
        for (int kk = 0; kk < TKK; kk++) {
            float a[4], bg[4], bu[4];
            #pragma unroll
            for (int i = 0; i < 4; i++) a[i] = As[kk][ty + 16 * i];
            #pragma unroll
            for (int j = 0; j < 4; j++) {
                bg[j] = Bg[kk][tx + 16 * j];
                bu[j] = Bu[kk][tx + 16 * j];
            }
            #pragma unroll
            for (int i = 0; i < 4; i++)
                #pragma unroll
                for (int j = 0; j < 4; j++) {
                    cg[i][j] += a[i] * bg[j];
                    cu[i][j] += a[i] * bu[j];
                }
        }
    }

    #pragma unroll
    for (int i = 0; i < 4; i++) {
        int m = m0 + ty + 16 * i;
        if (m < cnt) {
            float* arow = g_act + (size_t)(off + m) * NI + n0;
            #pragma unroll
            for (int j = 0; j < 4; j++) {
                float g = cg[i][j], u = cu[i][j];
                arow[tx + 16 * j] = (g / (1.0f + expf(-g))) * u;
            }
        }
    }
}

// ---------------- GEMM2: outp = act @ W2^T ----------------------------------
__global__ __launch_bounds__(256) void gemm2_kernel(
    const float* __restrict__ w2,
    const float* __restrict__ s2)
{
    int e   = blockIdx.y;
    int cnt = g_cnt[e];
    int m0  = blockIdx.z * TM;
    if (m0 >= cnt) return;
    int off = g_off[e];
    int n0  = blockIdx.x * TN;   // h in [0, NH)

    __shared__ float As[TKK][TM];
    __shared__ float Bs[TKK][TN];

    int tid = threadIdx.x;
    int tx = tid & 15;
    int ty = tid >> 4;
    int lr = tid >> 2;
    int lk = (tid & 3) << 2;

    int am = m0 + lr;
    if (am >= cnt) am = cnt - 1;
    const float* arow = g_act + (size_t)(off + am) * NI;
    const float* wr   = w2 + ((size_t)e * NH + (size_t)(n0 + lr)) * NI;
    const float* se   = s2 + (size_t)e * (NH / 128) * (NI / 128);
    int sBase = (n0 >> 7) * (NI / 128);

    float c[4][4];
    #pragma unroll
    for (int i = 0; i < 4; i++)
        #pragma unroll
        for (int j = 0; j < 4; j++) c[i][j] = 0.f;

    for (int k0 = 0; k0 < NI; k0 += TKK) {
        float4 av = *(const float4*)(arow + k0 + lk);
        float4 bv = *(const float4*)(wr + k0 + lk);
        float s = se[sBase + (k0 >> 7)];
        __syncthreads();
        As[lk + 0][lr] = av.x;  As[lk + 1][lr] = av.y;
        As[lk + 2][lr] = av.z;  As[lk + 3][lr] = av.w;
        Bs[lk + 0][lr] = bv.x * s; Bs[lk + 1][lr] = bv.y * s;
        Bs[lk + 2][lr] = bv.z * s; Bs[lk + 3][lr] = bv.w * s;
        __syncthreads();
        #pragma unroll
        for (int kk = 0; kk < TKK; kk++) {
            float a[4], b[4];
            #pragma unroll
            for (int i = 0; i < 4; i++) a[i] = As[kk][ty + 16 * i];
            #pragma unroll
            for (int j = 0; j < 4; j++) b[j] = Bs[kk][tx + 16 * j];
            #pragma unroll
            for (int i = 0; i < 4; i++)
                #pragma unroll
                for (int j = 0; j < 4; j++) c[i][j] += a[i] * b[j];
        }
    }

    #pragma unroll
    for (int i = 0; i < 4; i++) {
        int m = m0 + ty + 16 * i;
        if (m < cnt) {
            int orig = g_orig[off + m];
            float* orow = g_outp + (size_t)orig * NH + n0;
            #pragma unroll
            for (int j = 0; j < 4; j++) orow[tx + 16 * j] = c[i][j];
        }
    }
}

// ---------------- combine: out[t] = w[2t]*op[2t] + w[2t+1]*op[2t+1] ---------
__global__ void combine_kernel(const float* __restrict__ tw,
                               float* __restrict__ out)
{
    int idx = blockIdx.x * blockDim.x + threadIdx.x;
    if (idx >= NT * NH) return;
    int t = idx >> 11;     // / NH
    int h = idx & (NH - 1);
    out[idx] = tw[2 * t]     * g_outp[(size_t)(2 * t) * NH + h]
             + tw[2 * t + 1] * g_outp[(size_t)(2 * t + 1) * NH + h];
}

// ---------------- launch -----------------------------------------------------
extern "C" void kernel_launch(void* const* d_in, const int* in_sizes, int n_in,
                              void* d_out, int out_size) {
    const float* x   = (const float*)d_in[0];
    const void*  ids = d_in[1];
    const float* tw  = (const float*)d_in[2];
    const float* w13 = (const float*)d_in[3];
    const float* s13 = (const float*)d_in[4];
    const float* w2  = (const float*)d_in[5];
    const float* s2  = (const float*)d_in[6];
    float* out = (float*)d_out;

    route_kernel<<<1, 256>>>(ids);
    gemm1_kernel<<<dim3(NI / TN, NE, NPAIR / TM), 256>>>(x, w13, s13);
    gemm2_kernel<<<dim3(NH / TN, NE, NPAIR / TM), 256>>>(w2, s2);
    combine_kernel<<<(NT * NH + 255) / 256, 256>>>(tw, out);
}

// round 3
// speedup vs baseline: 3.7567x; 3.7567x over previous
#include <cuda_runtime.h>
#include <cuda_bf16.h>
#include <math.h>
#include <stdint.h>

#define NE 8
#define NH 2048
#define NI 2816
#define NT 512
#define NPAIR 1024
#define ASTR 24   // smem row stride in bf16 elems (16 + 8 pad -> conflict-free ldmatrix)

// ---------------- scratch (device globals; no allocation allowed) -----------
__device__ __align__(256) float g_act[(size_t)NPAIR * NI];
__device__ __align__(256) float g_outp[(size_t)NPAIR * NH];
__device__ int g_cnt[NE];
__device__ int g_off[NE];
__device__ int g_cur[NE];
__device__ int g_tok[NPAIR];
__device__ int g_orig[NPAIR];

// ---------------- routing ---------------------------------------------------
__global__ void route_kernel(const void* __restrict__ ids_raw) {
    __shared__ int s_or;
    int tid = threadIdx.x;
    if (tid == 0) s_or = 0;
    if (tid < NE) { g_cnt[tid] = 0; g_cur[tid] = 0; }
    __syncthreads();

    const int* i32 = (const int*)ids_raw;
    int acc = 0;
    for (int i = 1 + 2 * tid; i < NPAIR; i += 2 * blockDim.x) acc |= i32[i];
    atomicOr(&s_or, acc);
    __syncthreads();
    const bool is64 = (s_or == 0);
    const long long* i64 = (const long long*)ids_raw;

    for (int p = tid; p < NPAIR; p += blockDim.x) {
        int e = is64 ? (int)i64[p] : i32[p];
        atomicAdd(&g_cnt[e], 1);
    }
    __syncthreads();
    if (tid == 0) {
        int o = 0;
        for (int e = 0; e < NE; e++) { g_off[e] = o; o += g_cnt[e]; }
    }
    __syncthreads();
    for (int p = tid; p < NPAIR; p += blockDim.x) {
        int e = is64 ? (int)i64[p] : i32[p];
        int pos = g_off[e] + atomicAdd(&g_cur[e], 1);
        g_tok[pos]  = p >> 1;
        g_orig[pos] = p;
    }
}

// ---------------- MMA helpers ------------------------------------------------
__device__ __forceinline__ uint32_t sptr(const void* p) {
    return (uint32_t)__cvta_generic_to_shared(p);
}
__device__ __forceinline__ void ldsm4(uint32_t& r0, uint32_t& r1, uint32_t& r2,
                                      uint32_t& r3, uint32_t a) {
    asm volatile("ldmatrix.sync.aligned.m8n8.x4.shared.b16 {%0,%1,%2,%3}, [%4];"
                 : "=r"(r0), "=r"(r1), "=r"(r2), "=r"(r3) : "r"(a));
}
__device__ __forceinline__ void mma_bf16(float c[4], uint32_t a0, uint32_t a1,
                                         uint32_t a2, uint32_t a3,
                                         uint32_t b0, uint32_t b1) {
    asm volatile("mma.sync.aligned.m16n8k16.row.col.f32.bf16.bf16.f32 "
                 "{%0,%1,%2,%3}, {%4,%5,%6,%7}, {%8,%9}, {%0,%1,%2,%3};"
                 : "+f"(c[0]), "+f"(c[1]), "+f"(c[2]), "+f"(c[3])
                 : "r"(a0), "r"(a1), "r"(a2), "r"(a3), "r"(b0), "r"(b1));
}
__device__ __forceinline__ uint32_t packbf(float v0, float v1) {
    __nv_bfloat162 h = __floats2bfloat162_rn(v0, v1);
    return *reinterpret_cast<uint32_t*>(&h);
}

// Convert 8 fp32 (one k-run of 8) to bf16 hi/lo and store 16B each.
__device__ __forceinline__ void cvt_store_A(__nv_bfloat16* A_hi, __nv_bfloat16* A_lo,
                                            int idx, float4 r0, float4 r1) {
    float av[8] = {r0.x, r0.y, r0.z, r0.w, r1.x, r1.y, r1.z, r1.w};
    uint32_t ph[4], pl[4];
#pragma unroll
    for (int i = 0; i < 4; i++) {
        float v0 = av[2 * i], v1 = av[2 * i + 1];
        float h0 = __bfloat162float(__float2bfloat16_rn(v0));
        float h1 = __bfloat162float(__float2bfloat16_rn(v1));
        ph[i] = packbf(v0, v1);
        pl[i] = packbf(v0 - h0, v1 - h1);
    }
    *reinterpret_cast<uint4*>(A_hi + idx) = make_uint4(ph[0], ph[1], ph[2], ph[3]);
    *reinterpret_cast<uint4*>(A_lo + idx) = make_uint4(pl[0], pl[1], pl[2], pl[3]);
}
__device__ __forceinline__ void cvt_store_B8(__nv_bfloat16* B, int idx, float4 r0, float4 r1) {
    *reinterpret_cast<uint4*>(B + idx) =
        make_uint4(packbf(r0.x, r0.y), packbf(r0.z, r0.w),
                   packbf(r1.x, r1.y), packbf(r1.z, r1.w));
}

// ---------------- GEMM1: act = silu(x@Wg^T)*(x@Wu^T), grouped by expert ------
// Block: 128 m x 64 n (gate) + 64 n (up). Warps 0-3 gate, 4-7 up.
// smem stage (bf16 elems): A_hi[0,3072) A_lo[3072,6144) B[6144,9216) ; 2 stages.
#define G1_STAGE 9216
#define G1_NCH (NH / 16)

__global__ __launch_bounds__(256) void gemm1_kernel(
    const float* __restrict__ x,
    const float* __restrict__ w13,
    const float* __restrict__ s13)
{
    int e = blockIdx.y;
    int cnt = g_cnt[e];
    int m0 = blockIdx.z * 128;
    if (m0 >= cnt) return;
    int off = g_off[e];
    int n0 = blockIdx.x * 64;

    __shared__ __align__(16) unsigned char smem_raw[2 * G1_STAGE * 2];
    __nv_bfloat16* sb = (__nv_bfloat16*)smem_raw;

    int tid = threadIdx.x;
    int lane = tid & 31;
    int warp = tid >> 5;
    int half = warp >> 2;        // 0 = gate, 1 = up
    int wm = (warp & 3) * 32;

    // loaders: 2 threads per row, 8 k each
    int lr = tid >> 1;
    int lk = (tid & 1) * 8;
    int am = m0 + lr; if (am >= cnt) am = cnt - 1;
    const float* ap = x + (size_t)g_tok[off + am] * NH + lk;
    int wrow = (lr < 64) ? (n0 + lr) : (NI + n0 + (lr - 64));
    const float* bp = w13 + ((size_t)e * (2 * NI) + wrow) * NH + lk;
    int sA_idx = lr * ASTR + lk;
    int sB_idx = 6144 + lr * ASTR + lk;

    // per-warp-half block scale
    const float* sp = s13 + (size_t)e * (2 * NI / 128) * (NH / 128)
                    + (size_t)((half ? (n0 + NI) : n0) >> 7) * (NH / 128);
    float s_cur = sp[0];

    float acc[2][8][4];
#pragma unroll
    for (int a = 0; a < 2; a++)
#pragma unroll
        for (int b = 0; b < 8; b++)
#pragma unroll
            for (int c = 0; c < 4; c++) acc[a][b][c] = 0.f;

    // prologue: chunk 0
    float4 ra0 = *(const float4*)(ap);
    float4 ra1 = *(const float4*)(ap + 4);
    float4 rb0 = *(const float4*)(bp);
    float4 rb1 = *(const float4*)(bp + 4);
    cvt_store_A(sb, sb + 3072, sA_idx, ra0, ra1);
    cvt_store_B8(sb, sB_idx, rb0, rb1);
    __syncthreads();

    for (int kc = 0; kc < G1_NCH; kc++) {
        int cur = kc & 1;
        bool more = (kc + 1 < G1_NCH);
        if (more) {
            const float* a2 = ap + (kc + 1) * 16;
            const float* b2 = bp + (kc + 1) * 16;
            ra0 = *(const float4*)(a2);
            ra1 = *(const float4*)(a2 + 4);
            rb0 = *(const float4*)(b2);
            rb1 = *(const float4*)(b2 + 4);
        }
        // compute current stage
        {
            const __nv_bfloat16* A_hi = sb + cur * G1_STAGE;
            const __nv_bfloat16* A_lo = A_hi + 3072;
            const __nv_bfloat16* B = A_hi + 6144 + half * 64 * ASTR;
            uint32_t bf[8][2];
#pragma unroll
            for (int p = 0; p < 4; p++) {
                int row = p * 16 + ((lane >> 4) << 3) + (lane & 7);
                int col = ((lane >> 3) & 1) * 8;
                uint32_t r0, r1, r2, r3;
                ldsm4(r0, r1, r2, r3, sptr(B + row * ASTR + col));
                bf[2 * p][0] = r0; bf[2 * p][1] = r1;
                bf[2 * p + 1][0] = r2; bf[2 * p + 1][1] = r3;
            }
#pragma unroll
            for (int mt = 0; mt < 2; mt++) {
                int row = wm + mt * 16 + (((lane >> 3) & 1) << 3) + (lane & 7);
                int col = (lane >> 4) * 8;
                uint32_t h0, h1, h2, h3, l0, l1, l2, l3;
                ldsm4(h0, h1, h2, h3, sptr(A_hi + row * ASTR + col));
                ldsm4(l0, l1, l2, l3, sptr(A_lo + row * ASTR + col));
#pragma unroll
                for (int nt = 0; nt < 8; nt++) {
                    mma_bf16(acc[mt][nt], h0, h1, h2, h3, bf[nt][0], bf[nt][1]);
                    mma_bf16(acc[mt][nt], l0, l1, l2, l3, bf[nt][0], bf[nt][1]);
                }
            }
        }
        // rescale at 128-k block boundary
        if ((kc & 7) == 7 && more) {
            float s_next = sp[(kc >> 3) + 1];
            float r = s_cur / s_next;
#pragma unroll
            for (int a = 0; a < 2; a++)
#pragma unroll
                for (int b = 0; b < 8; b++)
#pragma unroll
                    for (int c = 0; c < 4; c++) acc[a][b][c] *= r;
            s_cur = s_next;
        }
        if (more) {
            __nv_bfloat16* st = sb + (cur ^ 1) * G1_STAGE;
            cvt_store_A(st, st + 3072, sA_idx, ra0, ra1);
            cvt_store_B8(st, sB_idx, rb0, rb1);
            __syncthreads();
        }
    }

    // final scale
#pragma unroll
    for (int a = 0; a < 2; a++)
#pragma unroll
        for (int b = 0; b < 8; b++)
#pragma unroll
            for (int c = 0; c < 4; c++) acc[a][b][c] *= s_cur;

    // epilogue: up warps publish to smem, gate warps fuse SwiGLU and store
    __syncthreads();
    float* ub = (float*)smem_raw;   // [128][64]
    if (half == 1) {
#pragma unroll
        for (int mt = 0; mt < 2; mt++)
#pragma unroll
            for (int cg = 0; cg < 2; cg++) {
                int row = wm + mt * 16 + (lane >> 2) + cg * 8;
#pragma unroll
                for (int nt = 0; nt < 8; nt++) {
                    int col = nt * 8 + (lane & 3) * 2;
                    ub[row * 64 + col]     = acc[mt][nt][cg * 2];
                    ub[row * 64 + col + 1] = acc[mt][nt][cg * 2 + 1];
                }
            }
    }
    __syncthreads();
    if (half == 0) {
#pragma unroll
        for (int mt = 0; mt < 2; mt++)
#pragma unroll
            for (int cg = 0; cg < 2; cg++) {
                int row = wm + mt * 16 + (lane >> 2) + cg * 8;
                int m = m0 + row;
                if (m < cnt) {
                    float* dst = g_act + (size_t)(off + m) * NI + n0;
#pragma unroll
                    for (int nt = 0; nt < 8; nt++) {
                        int col = nt * 8 + (lane & 3) * 2;
                        float g0 = acc[mt][nt][cg * 2];
                        float g1 = acc[mt][nt][cg * 2 + 1];
                        float u0 = ub[row * 64 + col];
                        float u1 = ub[row * 64 + col + 1];
                        dst[col]     = u0 * (g0 / (1.f + expf(-g0)));
                        dst[col + 1] = u1 * (g1 / (1.f + expf(-g1)));
                    }
                }
            }
    }
}

// ---------------- GEMM2: outp = act @ W2^T -----------------------------------
// Block: 128 m x 64 n. 8 warps in 4x2, warp tile 32x32.
// smem stage (bf16 elems): A_hi[0,3072) A_lo[3072,6144) B[6144,7680) ; 2 stages.
#define G2_STAGE 7680
#define G2_NCH (NI / 16)

__global__ __launch_bounds__(256) void gemm2_kernel(
    const float* __restrict__ w2,
    const float* __restrict__ s2)
{
    int e = blockIdx.y;
    int cnt = g_cnt[e];
    int m0 = blockIdx.z * 128;
    if (m0 >= cnt) return;
    int off = g_off[e];
    int n0 = blockIdx.x * 64;

    __shared__ __align__(16) unsigned char smem_raw[2 * G2_STAGE * 2];
    __nv_bfloat16* sb = (__nv_bfloat16*)smem_raw;

    int tid = threadIdx.x;
    int lane = tid & 31;
    int warp = tid >> 5;
    int wm = (warp >> 1) * 32;
    int wn = (warp & 1) * 32;

    int lr = tid >> 1;
    int lk = (tid & 1) * 8;
    int am = m0 + lr; if (am >= cnt) am = cnt - 1;
    const float* ap = g_act + (size_t)(off + am) * NI + lk;
    int rb = tid >> 2;
    int kb4 = (tid & 3) * 4;
    const float* bp = w2 + ((size_t)e * NH + n0 + rb) * NI + kb4;
    int sA_idx = lr * ASTR + lk;
    int sB_idx = 6144 + rb * ASTR + kb4;

    const float* sp = s2 + (size_t)e * (NH / 128) * (NI / 128)
                    + (size_t)(n0 >> 7) * (NI / 128);
    float s_cur = sp[0];

    float acc[2][4][4];
#pragma unroll
    for (int a = 0; a < 2; a++)
#pragma unroll
        for (int b = 0; b < 4; b++)
#pragma unroll
            for (int c = 0; c < 4; c++) acc[a][b][c] = 0.f;

    float4 ra0 = *(const float4*)(ap);
    float4 ra1 = *(const float4*)(ap + 4);
    float4 rb0 = *(const float4*)(bp);
    cvt_store_A(sb, sb + 3072, sA_idx, ra0, ra1);
    *reinterpret_cast<uint2*>(sb + sB_idx) =
        make_uint2(packbf(rb0.x, rb0.y), packbf(rb0.z, rb0.w));
    __syncthreads();

    for (int kc = 0; kc < G2_NCH; kc++) {
        int cur = kc & 1;
        bool more = (kc + 1 < G2_NCH);
        if (more) {
            const float* a2 = ap + (kc + 1) * 16;
            const float* b2 = bp + (kc + 1) * 16;
            ra0 = *(const float4*)(a2);
            ra1 = *(const float4*)(a2 + 4);
            rb0 = *(const float4*)(b2);
        }
        {
            const __nv_bfloat16* A_hi = sb + cur * G2_STAGE;
            const __nv_bfloat16* A_lo = A_hi + 3072;
            const __nv_bfloat16* B = A_hi + 6144 + wn * ASTR;
            uint32_t bf[4][2];
#pragma unroll
            for (int p = 0; p < 2; p++) {
                int row = p * 16 + ((lane >> 4) << 3) + (lane & 7);
                int col = ((lane >> 3) & 1) * 8;
                uint32_t r0, r1, r2, r3;
                ldsm4(r0, r1, r2, r3, sptr(B + row * ASTR + col));
                bf[2 * p][0] = r0; bf[2 * p][1] = r1;
                bf[2 * p + 1][0] = r2; bf[2 * p + 1][1] = r3;
            }
#pragma unroll
            for (int mt = 0; mt < 2; mt++) {
                int row = wm + mt * 16 + (((lane >> 3) & 1) << 3) + (lane & 7);
                int col = (lane >> 4) * 8;
                uint32_t h0, h1, h2, h3, l0, l1, l2, l3;
                ldsm4(h0, h1, h2, h3, sptr(A_hi + row * ASTR + col));
                ldsm4(l0, l1, l2, l3, sptr(A_lo + row * ASTR + col));
#pragma unroll
                for (int nt = 0; nt < 4; nt++) {
                    mma_bf16(acc[mt][nt], h0, h1, h2, h3, bf[nt][0], bf[nt][1]);
                    mma_bf16(acc[mt][nt], l0, l1, l2, l3, bf[nt][0], bf[nt][1]);
                }
            }
        }
        if ((kc & 7) == 7 && more) {
            float s_next = sp[(kc >> 3) + 1];
            float r = s_cur / s_next;
#pragma unroll
            for (int a = 0; a < 2; a++)
#pragma unroll
                for (int b = 0; b < 4; b++)
#pragma unroll
                    for (int c = 0; c < 4; c++) acc[a][b][c] *= r;
            s_cur = s_next;
        }
        if (more) {
            __nv_bfloat16* st = sb + (cur ^ 1) * G2_STAGE;
            cvt_store_A(st, st + 3072, sA_idx, ra0, ra1);
            *reinterpret_cast<uint2*>(st + sB_idx) =
                make_uint2(packbf(rb0.x, rb0.y), packbf(rb0.z, rb0.w));
            __syncthreads();
        }
    }

#pragma unroll
    for (int mt = 0; mt < 2; mt++)
#pragma unroll
        for (int cg = 0; cg < 2; cg++) {
            int row = wm + mt * 16 + (lane >> 2) + cg * 8;
            int m = m0 + row;
            if (m < cnt) {
                int orig = g_orig[off + m];
                float* dst = g_outp + (size_t)orig * NH + n0 + wn;
#pragma unroll
                for (int nt = 0; nt < 4; nt++) {
                    int col = nt * 8 + (lane & 3) * 2;
                    float2 v = make_float2(acc[mt][nt][cg * 2] * s_cur,
                                           acc[mt][nt][cg * 2 + 1] * s_cur);
                    *reinterpret_cast<float2*>(dst + col) = v;
                }
            }
        }
}

// ---------------- combine ----------------------------------------------------
__global__ void combine_kernel(const float* __restrict__ tw,
                               float* __restrict__ out)
{
    int idx = blockIdx.x * blockDim.x + threadIdx.x;
    if (idx >= NT * NH) return;
    int t = idx >> 11;
    int h = idx & (NH - 1);
    out[idx] = tw[2 * t]     * g_outp[(size_t)(2 * t) * NH + h]
             + tw[2 * t + 1] * g_outp[(size_t)(2 * t + 1) * NH + h];
}

// ---------------- launch -----------------------------------------------------
extern "C" void kernel_launch(void* const* d_in, const int* in_sizes, int n_in,
                              void* d_out, int out_size) {
    const float* x   = (const float*)d_in[0];
    const void*  ids = d_in[1];
    const float* tw  = (const float*)d_in[2];
    const float* w13 = (const float*)d_in[3];
    const float* s13 = (const float*)d_in[4];
    const float* w2  = (const float*)d_in[5];
    const float* s2  = (const float*)d_in[6];
    float* out = (float*)d_out;

    route_kernel<<<1, 256>>>(ids);
    gemm1_kernel<<<dim3(NI / 64, NE, NPAIR / 128), 256>>>(x, w13, s13);
    gemm2_kernel<<<dim3(NH / 64, NE, NPAIR / 128), 256>>>(w2, s2);
    combine_kernel<<<(NT * NH + 255) / 256, 256>>>(tw, out);
}